// round 13
// baseline (speedup 1.0000x reference)
#include <cuda_runtime.h>
#include <cuda_fp16.h>
#include <math.h>
#include <stdint.h>

#define D_    1024
#define H_    16
#define HD_   64
#define S_    2048
#define B_    4
#define T_    (B_*S_)      // 8192 tokens
#define DFF_  4096
#define SIXD_ 6144

// ---------------- scratch (static device globals; no allocation) ----------------
__device__ float  g_mod [B_*SIXD_];
__device__ __half g_xn  [(size_t)T_*D_];
__device__ __half g_qkv [(size_t)T_*3*D_];
__device__ __half g_q   [(size_t)B_*H_*S_*HD_];
__device__ __half g_k   [(size_t)B_*H_*S_*HD_];
__device__ __half g_v   [(size_t)B_*H_*S_*HD_];   // pair-interleaved: [bh][s/2][hd][2]
__device__ __half g_attn[(size_t)T_*D_];
__device__ float  g_x2  [(size_t)T_*D_];
__device__ __half g_h   [(size_t)T_*DFF_];
// half, k-pair-interleaved weights: wh2[k2][n] = (W[2k2][n], W[2k2+1][n])
__device__ __half g_wqkv[(size_t)D_*3*D_];
__device__ __half g_wout[(size_t)D_*D_];
__device__ __half g_w1  [(size_t)D_*DFF_];
__device__ __half g_w2  [(size_t)DFF_*D_];

// ---------------- async copy / mma helpers ---------------------------------------
__device__ __forceinline__ void cp_async16(void* smem, const void* gmem)
{
    uint32_t sa = (uint32_t)__cvta_generic_to_shared(smem);
    asm volatile("cp.async.cg.shared.global [%0], [%1], 16;\n"
                 :: "r"(sa), "l"(gmem));
}
#define CP_COMMIT()  asm volatile("cp.async.commit_group;\n" ::: "memory")
#define CP_WAITALL() asm volatile("cp.async.wait_all;\n" ::: "memory")

// fp16 m16n8k16, fp32 accumulate
__device__ __forceinline__ void mma_f16(float* c, const uint32_t* a,
                                        const uint32_t* b)
{
    asm volatile("mma.sync.aligned.m16n8k16.row.col.f32.f16.f16.f32 "
                 "{%0,%1,%2,%3}, {%4,%5,%6,%7}, {%8,%9}, {%0,%1,%2,%3};\n"
                 : "+f"(c[0]), "+f"(c[1]), "+f"(c[2]), "+f"(c[3])
                 : "r"(a[0]), "r"(a[1]), "r"(a[2]), "r"(a[3]),
                   "r"(b[0]), "r"(b[1]));
}

__device__ __forceinline__ uint32_t pack2(float lo, float hi)
{
    __half2 h = __floats2half2_rn(lo, hi);
    return *(uint32_t*)&h;
}

// ---------------- merged weight convert + k-pair interleave -----------------------
// segments: [0,1536) Wqkv N=3072 | [1536,2048) Wout N=1024 |
//           [2048,4096) W1 N=4096 | [4096,6144) W2 N=1024 (K=4096)
__global__ void wconv_all(const float* __restrict__ Wqkv,
                          const float* __restrict__ Wout,
                          const float* __restrict__ W1,
                          const float* __restrict__ W2,
                          __half* __restrict__ o_qkv,
                          __half* __restrict__ o_out,
                          __half* __restrict__ o_w1,
                          __half* __restrict__ o_w2)
{
    int bid = blockIdx.x;
    const float* in;  __half* out;  int N;  int base;
    if (bid < 1536)      { in = Wqkv; out = o_qkv; N = 3*D_; base = 0; }
    else if (bid < 2048) { in = Wout; out = o_out; N = D_;   base = 1536; }
    else if (bid < 4096) { in = W1;   out = o_w1;  N = DFF_; base = 2048; }
    else                 { in = W2;   out = o_w2;  N = D_;   base = 4096; }
    int idx = (bid - base)*256 + threadIdx.x;
    int k2 = idx / (N >> 2);
    int nc = (idx - k2*(N >> 2)) * 4;
    float4 e = *(const float4*)(in + (size_t)(2*k2    )*N + nc);
    float4 o = *(const float4*)(in + (size_t)(2*k2 + 1)*N + nc);
    uint4 r;
    r.x = pack2(e.x, o.x);  r.y = pack2(e.y, o.y);
    r.z = pack2(e.z, o.z);  r.w = pack2(e.w, o.w);
    *(uint4*)(out + ((size_t)k2*N + nc)*2) = r;
}

// ---------------- adaLN modulation ------------------------------------------------
__global__ void mod_kernel(const float* __restrict__ c,
                           const float* __restrict__ adaW,
                           const float* __restrict__ adab,
                           float* __restrict__ mod)
{
    int b = blockIdx.y;
    int j = blockIdx.x * 256 + threadIdx.x;
    __shared__ float cs[D_];
    for (int i = threadIdx.x; i < D_; i += 256) cs[i] = c[b*D_ + i];
    __syncthreads();
    float acc = adab[j];
#pragma unroll 4
    for (int k = 0; k < D_; k++)
        acc = fmaf(cs[k], adaW[(size_t)k*SIXD_ + j], acc);
    mod[b*SIXD_ + j] = acc;
}

// ---------------- LayerNorm + modulate (half output) ------------------------------
__global__ void ln_mod_kernel(const float* __restrict__ x,
                              const float* __restrict__ w,
                              const float* __restrict__ mod,
                              __half* __restrict__ out,
                              int sh_off, int sc_off)
{
    int t = blockIdx.x;
    int b = t / S_;
    int tid = threadIdx.x;
    float4 v = ((const float4*)(x + (size_t)t*D_))[tid];
    float s  = v.x + v.y + v.z + v.w;
    float sq = v.x*v.x + v.y*v.y + v.z*v.z + v.w*v.w;
#pragma unroll
    for (int o = 16; o > 0; o >>= 1) {
        s  += __shfl_xor_sync(0xffffffffu, s,  o);
        sq += __shfl_xor_sync(0xffffffffu, sq, o);
    }
    __shared__ float ss[8], ssq[8];
    int warp = tid >> 5, lane = tid & 31;
    if (lane == 0) { ss[warp] = s; ssq[warp] = sq; }
    __syncthreads();
    if (warp == 0) {
        s  = (lane < 8) ? ss[lane]  : 0.f;
        sq = (lane < 8) ? ssq[lane] : 0.f;
#pragma unroll
        for (int o = 4; o > 0; o >>= 1) {
            s  += __shfl_xor_sync(0xffffffffu, s,  o);
            sq += __shfl_xor_sync(0xffffffffu, sq, o);
        }
        if (lane == 0) { ss[0] = s; ssq[0] = sq; }
    }
    __syncthreads();
    s = ss[0]; sq = ssq[0];
    float mu   = s  * (1.f/D_);
    float var  = sq * (1.f/D_) - mu*mu;
    float rsig = rsqrtf(var + 1e-5f);

    const float* modb = mod + b*SIXD_;
    float4 wv  = ((const float4*)w)[tid];
    float4 shv = ((const float4*)(modb + sh_off))[tid];
    float4 scv = ((const float4*)(modb + sc_off))[tid];
    uint2 r;
    r.x = pack2(fmaf((v.x-mu)*rsig*wv.x, (1.f+scv.x), shv.x),
                fmaf((v.y-mu)*rsig*wv.y, (1.f+scv.y), shv.y));
    r.y = pack2(fmaf((v.z-mu)*rsig*wv.z, (1.f+scv.z), shv.z),
                fmaf((v.w-mu)*rsig*wv.w, (1.f+scv.w), shv.w));
    *(uint2*)(out + (size_t)t*D_ + tid*4) = r;
}

// ---------------- RMSNorm(q,k) + RoPE + relayout (half out) -----------------------
// q scale folds softmax 1/sqrt(HD) AND log2(e)
#define QSCALE 0.1803368801111204f
__global__ void qk_rope_kernel(const __half* __restrict__ qkv,
                               const float* __restrict__ cosp,
                               const float* __restrict__ sinp,
                               const float* __restrict__ qw,
                               const float* __restrict__ kw,
                               __half* __restrict__ Q,
                               __half* __restrict__ K,
                               __half* __restrict__ V)
{
    int t = blockIdx.x;
    int s = t % S_;
    int b = t / S_;
    int h    = threadIdx.x >> 5;
    int lane = threadIdx.x & 31;
    const __half* base = qkv + (size_t)t*3*D_ + h*HD_;
    float q0 = __half2float(base[lane]);
    float q1 = __half2float(base[lane+32]);
    float k0 = __half2float(base[D_+lane]);
    float k1 = __half2float(base[D_+lane+32]);
    float v0 = __half2float(base[2*D_+lane]);
    float v1 = __half2float(base[2*D_+lane+32]);

    float qs = q0*q0 + q1*q1;
    float ks = k0*k0 + k1*k1;
#pragma unroll
    for (int o = 16; o > 0; o >>= 1) {
        qs += __shfl_xor_sync(0xffffffffu, qs, o);
        ks += __shfl_xor_sync(0xffffffffu, ks, o);
    }
    float qr = rsqrtf(qs*(1.f/HD_) + 1e-6f);
    float kr = rsqrtf(ks*(1.f/HD_) + 1e-6f);
    q0 *= qr*qw[lane];  q1 *= qr*qw[lane+32];
    k0 *= kr*kw[lane];  k1 *= kr*kw[lane+32];

    float c0 = cosp[s*HD_+lane], c1 = cosp[s*HD_+lane+32];
    float n0 = sinp[s*HD_+lane], n1 = sinp[s*HD_+lane+32];
    float qo0 = (q0*c0 - q1*n0) * QSCALE;
    float qo1 = (q1*c1 + q0*n1) * QSCALE;
    float ko0 =  k0*c0 - k1*n0;
    float ko1 =  k1*c1 + k0*n1;

    int bh = b*H_ + h;
    size_t o = ((size_t)bh*S_ + s)*HD_;
    Q[o+lane]    = __float2half_rn(qo0);
    Q[o+lane+32] = __float2half_rn(qo1);
    K[o+lane]    = __float2half_rn(ko0);
    K[o+lane+32] = __float2half_rn(ko1);
    size_t vb = ((size_t)bh*(S_/2) + (s >> 1))*HD_;
    V[(vb + lane   )*2 + (s & 1)] = __float2half_rn(v0);
    V[(vb + lane+32)*2 + (s & 1)] = __float2half_rn(v1);
}

// ================= fp16 tensor-core flash attention ===============================
// No online max (|s|<=8 bound); Q/P in registers; single barrier per KV tile:
// wait_all -> sync -> prefetch(next) -> compute.  K/V double-buffered.
#define AQT 128
#define AKT 64
#define QP2 36
#define KP2 36
#define VP2 72
#define QS_W (AQT*QP2)          // 4608 words
#define KS_W (AKT*KP2)          // 2304
#define VS_W ((AKT/2)*VP2)      // 2304
#define ATTN_SMEM ((QS_W + 2*(KS_W + VS_W)) * 4)   // 55296 B

__global__ __launch_bounds__(256, 2)
void attn_mma_kernel(const __half* __restrict__ Q,
                     const __half* __restrict__ K,
                     const __half* __restrict__ V,
                     __half* __restrict__ out)
{
    extern __shared__ uint32_t smu[];
    uint32_t* Qs = smu;
    uint32_t* Kst[2]; uint32_t* Vst[2];
    Kst[0] = Qs + QS_W;           Vst[0] = Kst[0] + KS_W;
    Kst[1] = Vst[0] + VS_W;       Vst[1] = Kst[1] + KS_W;

    int bh  = blockIdx.y;
    int qt  = blockIdx.x;
    int tid = threadIdx.x;
    int warp = tid >> 5, lane = tid & 31;
    int gid = lane >> 2, tig = lane & 3;
    int wm = warp * 16;

    const __half* Kb0 = K + (size_t)bh*S_*HD_;
    const __half* Vb0 = V + (size_t)bh*(S_/2)*HD_*2;

    // ---- prologue: Q tile + KV tile 0 --------------------------------------------
    const __half* Qb = Q + ((size_t)bh*S_ + qt*AQT)*HD_;
    {
        int qr = tid >> 1, qc2 = (tid & 1) * 16;
#pragma unroll
        for (int c = 0; c < 4; c++)
            cp_async16(&Qs[qr*QP2 + qc2 + c*4], Qb + qr*HD_ + (qc2 + c*4)*2);
    }
    {
        int kr = tid >> 2, kc2 = (tid & 3) * 8;
        const __half* Kb = Kb0 + (size_t)kr*HD_;
        cp_async16(&Kst[0][kr*KP2 + kc2    ], Kb + kc2*2);
        cp_async16(&Kst[0][kr*KP2 + kc2 + 4], Kb + kc2*2 + 8);
        int vr = tid >> 3, vc2 = (tid & 7) * 8;
        const __half* Vb = Vb0 + ((size_t)vr*HD_ + vc2)*2;
        cp_async16(&Vst[0][vr*VP2 + vc2    ], Vb);
        cp_async16(&Vst[0][vr*VP2 + vc2 + 4], Vb + 8);
    }
    CP_COMMIT();

    float l0 = 0.f, l1 = 0.f;        // per-thread partial row sums
    float oacc[8][4];
#pragma unroll
    for (int j = 0; j < 8; j++)
#pragma unroll
        for (int q = 0; q < 4; q++) oacc[j][q] = 0.f;

    uint32_t qf[4][4];               // Q fragments (loaded at kt==0)

    const int NT = S_/AKT;
    for (int kt = 0; kt < NT; kt++) {
        int s = kt & 1;
        CP_WAITALL();          // tile kt resident
        __syncthreads();       // publishes stage s AND proves kt-1 compute done

        if (kt == 0) {
#pragma unroll
            for (int kc = 0; kc < 4; kc++) {
                const uint32_t* qp = Qs + (wm + gid)*QP2 + kc*8 + tig;
                qf[kc][0] = qp[0];
                qf[kc][1] = qp[8*QP2];
                qf[kc][2] = qp[4];
                qf[kc][3] = qp[8*QP2 + 4];
            }
        }

        if (kt + 1 < NT) {     // prefetch KV(kt+1) into stage s^1 (safe post-sync)
            int kr = tid >> 2, kc2 = (tid & 3) * 8;
            const __half* Kb = Kb0 + (size_t)((kt+1)*AKT + kr)*HD_;
            cp_async16(&Kst[s^1][kr*KP2 + kc2    ], Kb + kc2*2);
            cp_async16(&Kst[s^1][kr*KP2 + kc2 + 4], Kb + kc2*2 + 8);
            int vr = tid >> 3, vc2 = (tid & 7) * 8;
            const __half* Vb = Vb0 + ((size_t)((kt+1)*(AKT/2) + vr)*HD_ + vc2)*2;
            cp_async16(&Vst[s^1][vr*VP2 + vc2    ], Vb);
            cp_async16(&Vst[s^1][vr*VP2 + vc2 + 4], Vb + 8);
            CP_COMMIT();
        }

        const uint32_t* Ks = Kst[s];
        const uint32_t* Vs = Vst[s];

        // ---- S = Q @ K^T (scores pre-scaled by log2e/sqrt(HD)) -----------------
        float sacc[8][4];
#pragma unroll
        for (int j = 0; j < 8; j++)
#pragma unroll
            for (int q = 0; q < 4; q++) sacc[j][q] = 0.f;

#pragma unroll
        for (int kc = 0; kc < 4; kc++) {
#pragma unroll
            for (int j = 0; j < 8; j++) {
                uint32_t bf[2];
                const uint32_t* kp = Ks + (j*8 + gid)*KP2 + kc*8 + tig;
                bf[0] = kp[0];
                bf[1] = kp[4];
                mma_f16(sacc[j], qf[kc], bf);
            }
        }

        // ---- p = 2^s (no max-shift; fp16-safe) ---------------------------------
        uint32_t p2a[8], p2b[8];
#pragma unroll
        for (int j = 0; j < 8; j++) {
            __half2 pa = __floats2half2_rn(exp2f(sacc[j][0]), exp2f(sacc[j][1]));
            __half2 pb = __floats2half2_rn(exp2f(sacc[j][2]), exp2f(sacc[j][3]));
            float2 fa = __half22float2(pa);
            float2 fb = __half22float2(pb);
            l0 += fa.x + fa.y;  l1 += fb.x + fb.y;
            p2a[j] = *(uint32_t*)&pa;
            p2b[j] = *(uint32_t*)&pb;
        }

        // ---- O += P @ V (A-fragments direct from registers) --------------------
#pragma unroll
        for (int kc = 0; kc < 4; kc++) {
            uint32_t af[4];
            af[0] = p2a[2*kc];
            af[1] = p2b[2*kc];
            af[2] = p2a[2*kc + 1];
            af[3] = p2b[2*kc + 1];
#pragma unroll
            for (int j = 0; j < 8; j++) {
                uint32_t bf[2];
                const uint32_t* vp = Vs + (kc*8 + tig)*VP2 + j*8 + gid;
                bf[0] = vp[0];
                bf[1] = vp[4*VP2];
                mma_f16(oacc[j], af, bf);
            }
        }
        // no end barrier: next iteration's top sync protects stage reuse
    }

    // ---- final l reduction + epilogue -> g_attn (half) ---------------------------
    l0 += __shfl_xor_sync(0xffffffffu, l0, 1);
    l0 += __shfl_xor_sync(0xffffffffu, l0, 2);
    l1 += __shfl_xor_sync(0xffffffffu, l1, 1);
    l1 += __shfl_xor_sync(0xffffffffu, l1, 2);

    int b = bh >> 4, h = bh & 15;
    int r0 = qt*AQT + wm + gid;
    float inv0 = 1.f / l0, inv1 = 1.f / l1;
#pragma unroll
    for (int j = 0; j < 8; j++) {
        int col = h*HD_ + j*8 + 2*tig;
        *(__half2*)&out[((size_t)(b*S_ + r0    ))*D_ + col] =
            __floats2half2_rn(oacc[j][0]*inv0, oacc[j][1]*inv0);
        *(__half2*)&out[((size_t)(b*S_ + r0 + 8))*D_ + col] =
            __floats2half2_rn(oacc[j][2]*inv1, oacc[j][3]*inv1);
    }
}

// ================= fp16 tensor-core GEMM with fused epilogues =====================
// Block 128x128, GBK=64 (32 half2), 8 warps (2M x 4N), warp tile 64x32.
// Single barrier per K-iter: wait_all -> sync -> prefetch -> compute.
#define GBM 128
#define GBN 128
#define GBK 64
#define AP2 36
#define BP2 136

__device__ __forceinline__ float gelu_t(float x)
{
    float x3 = x*x*x;
    return 0.5f*x*(1.f + tanhf(0.7978845608028654f*(x + 0.044715f*x3)));
}

// MODE 0: C(half) = acc                       (QKV)
// MODE 1: C(float) = res + gate*acc           (out-proj + residual)
// MODE 2: C(half) = gelu(acc + bias)          (MLP up)
// MODE 3: C(float) = res + gate*(acc + bias)  (MLP down + residual)
template <int MODE>
__global__ __launch_bounds__(256)
void mma_gemm(const __half* __restrict__ A, const __half* __restrict__ Bm,
              void* __restrict__ Cv, int N, int K,
              const float* __restrict__ res, const float* __restrict__ bias,
              const float* __restrict__ mod, int gate_off)
{
    __shared__ uint32_t As[2][GBM*AP2];   // 36864 B
    __shared__ uint32_t Bs[2][32*BP2];    // 34816 B

    int tid  = threadIdx.x;
    int warp = tid >> 5, lane = tid & 31;
    int wm   = (warp >> 2) * 64;
    int wn   = (warp & 3)  * 32;
    int gid  = lane >> 2;
    int tig  = lane & 3;

    const __half* Ap = A  + (size_t)blockIdx.y * GBM * K;
    const __half* Bp = Bm + (size_t)blockIdx.x * GBN * 2;

    // A: row ar, 16 half2-words starting at aw (2 threads/row)
    int ar = tid >> 1;
    int aw = (tid & 1) * 16;
    // B: k2-row bk2 (0..31), 16 words at bn2 (8 threads/row)
    int bk2 = tid >> 3;
    int bn2 = (tid & 7) * 16;

    float acc[4][4][4];
#pragma unroll
    for (int i = 0; i < 4; i++)
#pragma unroll
        for (int j = 0; j < 4; j++)
#pragma unroll
            for (int q = 0; q < 4; q++) acc[i][j][q] = 0.f;

    // prologue: stage 0
    {
        const __half* ag = Ap + (size_t)ar*K + aw*2;
#pragma unroll
        for (int c = 0; c < 4; c++)
            cp_async16(&As[0][ar*AP2 + aw + c*4], ag + c*8);
        const __half* bg = Bp + ((size_t)bk2*N + bn2)*2;
#pragma unroll
        for (int c = 0; c < 4; c++)
            cp_async16(&Bs[0][bk2*BP2 + bn2 + c*4], bg + c*8);
    }
    CP_COMMIT();

    int buf = 0;
    for (int k0 = 0; k0 < K; k0 += GBK) {
        CP_WAITALL();
        __syncthreads();     // publishes buf AND proves previous compute done

        if (k0 + GBK < K) {  // prefetch into buf^1 (safe post-sync)
            const __half* ag = Ap + (size_t)ar*K + (k0 + GBK) + aw*2;
#pragma unroll
            for (int c = 0; c < 4; c++)
                cp_async16(&As[buf^1][ar*AP2 + aw + c*4], ag + c*8);
            const __half* bg = Bp + ((size_t)((k0 + GBK)/2 + bk2)*N + bn2)*2;
#pragma unroll
            for (int c = 0; c < 4; c++)
                cp_async16(&Bs[buf^1][bk2*BP2 + bn2 + c*4], bg + c*8);
            CP_COMMIT();
        }

        const uint32_t* as = As[buf];
        const uint32_t* bs = Bs[buf];
#pragma unroll
        for (int kc = 0; kc < 4; kc++) {          // 4 x k16 steps
            uint32_t af[4][4], bf[4][2];
#pragma unroll
            for (int i = 0; i < 4; i++) {
                int r0 = wm + i*16 + gid;
                const uint32_t* ap = as + r0*AP2 + kc*8 + tig;
                af[i][0] = ap[0];
                af[i][1] = ap[8*AP2];
                af[i][2] = ap[4];
                af[i][3] = ap[8*AP2 + 4];
            }
#pragma unroll
            for (int j = 0; j < 4; j++) {
                int n0 = wn + j*8 + gid;
                bf[j][0] = bs[(kc*8 + tig    )*BP2 + n0];
                bf[j][1] = bs[(kc*8 + tig + 4)*BP2 + n0];
            }
#pragma unroll
            for (int i = 0; i < 4; i++)
#pragma unroll
                for (int j = 0; j < 4; j++)
                    mma_f16(acc[i][j], af[i], bf[j]);
        }
        buf ^= 1;
        // no end barrier
    }

    int row_base = blockIdx.y*GBM + wm;
    int col_base = blockIdx.x*GBN + wn;
    int bb = (blockIdx.y * GBM) >> 11;
    const float* modb = (MODE == 1 || MODE == 3)
                      ? (mod + bb*SIXD_ + gate_off) : nullptr;
#pragma unroll
    for (int i = 0; i < 4; i++) {
        int r0 = row_base + i*16 + gid;
#pragma unroll
        for (int j = 0; j < 4; j++) {
            int c0 = col_base + j*8 + tig*2;
#pragma unroll
            for (int h = 0; h < 2; h++) {
                int row = r0 + h*8;
                float v0 = acc[i][j][h*2 + 0];
                float v1 = acc[i][j][h*2 + 1];
                if (MODE == 0) {
                    *(__half2*)((__half*)Cv + (size_t)row*N + c0) =
                        __floats2half2_rn(v0, v1);
                } else if (MODE == 1) {
                    float2 rv = *(const float2*)(res + (size_t)row*N + c0);
                    float2 st;
                    st.x = rv.x + modb[c0    ]*v0;
                    st.y = rv.y + modb[c0 + 1]*v1;
                    *(float2*)((float*)Cv + (size_t)row*N + c0) = st;
                } else if (MODE == 2) {
                    *(__half2*)((__half*)Cv + (size_t)row*N + c0) =
                        __floats2half2_rn(gelu_t(v0 + bias[c0]),
                                          gelu_t(v1 + bias[c0 + 1]));
                } else {
                    float2 rv = *(const float2*)(res + (size_t)row*N + c0);
                    float2 st;
                    st.x = rv.x + modb[c0    ]*(v0 + bias[c0]);
                    st.y = rv.y + modb[c0 + 1]*(v1 + bias[c0 + 1]);
                    *(float2*)((float*)Cv + (size_t)row*N + c0) = st;
                }
            }
        }
    }
}

// ---------------- launch ---------------------------------------------------------
extern "C" void kernel_launch(void* const* d_in, const int* in_sizes, int n_in,
                              void* d_out, int out_size)
{
    const float* x      = (const float*)d_in[0];
    const float* cosp   = (const float*)d_in[1];
    const float* sinp   = (const float*)d_in[2];
    const float* c      = (const float*)d_in[3];
    const float* n1w    = (const float*)d_in[4];
    const float* Wqkv   = (const float*)d_in[5];
    const float* Wout   = (const float*)d_in[6];
    const float* qw     = (const float*)d_in[7];
    const float* kw     = (const float*)d_in[8];
    const float* n2w    = (const float*)d_in[9];
    const float* W1     = (const float*)d_in[10];
    const float* b1     = (const float*)d_in[11];
    const float* W2     = (const float*)d_in[12];
    const float* b2     = (const float*)d_in[13];
    const float* adaW   = (const float*)d_in[14];
    const float* adab   = (const float*)d_in[15];
    float* out = (float*)d_out;

    float *p_mod, *p_x2;
    __half *p_xn, *p_qkv, *p_q, *p_k, *p_v, *p_attn, *p_h;
    __half *p_wqkv, *p_wout, *p_w1, *p_w2;
    cudaGetSymbolAddress((void**)&p_mod,  g_mod);
    cudaGetSymbolAddress((void**)&p_xn,   g_xn);
    cudaGetSymbolAddress((void**)&p_qkv,  g_qkv);
    cudaGetSymbolAddress((void**)&p_q,    g_q);
    cudaGetSymbolAddress((void**)&p_k,    g_k);
    cudaGetSymbolAddress((void**)&p_v,    g_v);
    cudaGetSymbolAddress((void**)&p_attn, g_attn);
    cudaGetSymbolAddress((void**)&p_x2,   g_x2);
    cudaGetSymbolAddress((void**)&p_h,    g_h);
    cudaGetSymbolAddress((void**)&p_wqkv, g_wqkv);
    cudaGetSymbolAddress((void**)&p_wout, g_wout);
    cudaGetSymbolAddress((void**)&p_w1,   g_w1);
    cudaGetSymbolAddress((void**)&p_w2,   g_w2);

    cudaFuncSetAttribute(attn_mma_kernel,
                         cudaFuncAttributeMaxDynamicSharedMemorySize, ATTN_SMEM);

    // 0. merged weight convert + k-pair interleave to half
    wconv_all<<<6144, 256>>>(Wqkv, Wout, W1, W2,
                             p_wqkv, p_wout, p_w1, p_w2);

    // 1. adaLN modulation
    mod_kernel<<<dim3(SIXD_/256, B_), 256>>>(c, adaW, adab, p_mod);
    // 2. LN1 + modulate -> half
    ln_mod_kernel<<<T_, 256>>>(x, n1w, p_mod, p_xn, 0, D_);
    // 3. QKV projection (fp16 mma) -> half
    mma_gemm<0><<<dim3(3*D_/GBN, T_/GBM), 256>>>(p_xn, p_wqkv, p_qkv,
                                                 3*D_, D_, nullptr, nullptr,
                                                 nullptr, 0);
    // 4. qk-RMSNorm + RoPE + relayout -> half (q pre-scaled by log2e/8)
    qk_rope_kernel<<<T_, 512>>>(p_qkv, cosp, sinp, qw, kw, p_q, p_k, p_v);
    // 5. attention (fp16 mma flash, no-max softmax, single-sync pipeline)
    attn_mma_kernel<<<dim3(S_/AQT, B_*H_), 256, ATTN_SMEM>>>(p_q, p_k, p_v,
                                                             p_attn);
    // 6. out-proj + gated residual (gate g_msa @2D) -> float
    mma_gemm<1><<<dim3(D_/GBN, T_/GBM), 256>>>(p_attn, p_wout, p_x2,
                                               D_, D_, x, nullptr,
                                               p_mod, 2*D_);
    // 7. LN2 + modulate (shift 3D, scale 4D) -> half
    ln_mod_kernel<<<T_, 256>>>(p_x2, n2w, p_mod, p_xn, 3*D_, 4*D_);
    // 8. MLP up + gelu -> half
    mma_gemm<2><<<dim3(DFF_/GBN, T_/GBM), 256>>>(p_xn, p_w1, p_h,
                                                 DFF_, D_, nullptr, b1,
                                                 nullptr, 0);
    // 9. MLP down + gated residual (gate g_mlp @5D) -> float (d_out)
    mma_gemm<3><<<dim3(D_/GBN, T_/GBM), 256>>>(p_h, p_w2, out,
                                               D_, DFF_, p_x2, b2,
                                               p_mod, 5*D_);
}

// round 14
// speedup vs baseline: 1.0662x; 1.0662x over previous
#include <cuda_runtime.h>
#include <cuda_fp16.h>
#include <math.h>
#include <stdint.h>

#define D_    1024
#define H_    16
#define HD_   64
#define S_    2048
#define B_    4
#define T_    (B_*S_)      // 8192 tokens
#define DFF_  4096
#define SIXD_ 6144

// ---------------- scratch (static device globals; no allocation) ----------------
__device__ float  g_mod [B_*SIXD_];
__device__ __half g_xn  [(size_t)T_*D_];
__device__ __half g_qkv [(size_t)T_*3*D_];
__device__ __half g_q   [(size_t)B_*H_*S_*HD_];
__device__ __half g_k   [(size_t)B_*H_*S_*HD_];
__device__ __half g_v   [(size_t)B_*H_*S_*HD_];   // pair-interleaved: [bh][s/2][hd][2]
__device__ __half g_attn[(size_t)T_*D_];
__device__ float  g_x2  [(size_t)T_*D_];
__device__ __half g_h   [(size_t)T_*DFF_];
// half, k-pair-interleaved weights: wh2[k2][n] = (W[2k2][n], W[2k2+1][n])
__device__ __half g_wqkv[(size_t)D_*3*D_];
__device__ __half g_wout[(size_t)D_*D_];
__device__ __half g_w1  [(size_t)D_*DFF_];
__device__ __half g_w2  [(size_t)DFF_*D_];

// ---------------- async copy / mma helpers ---------------------------------------
__device__ __forceinline__ void cp_async16(void* smem, const void* gmem)
{
    uint32_t sa = (uint32_t)__cvta_generic_to_shared(smem);
    asm volatile("cp.async.cg.shared.global [%0], [%1], 16;\n"
                 :: "r"(sa), "l"(gmem));
}
#define CP_COMMIT()  asm volatile("cp.async.commit_group;\n" ::: "memory")
#define CP_WAIT1()   asm volatile("cp.async.wait_group 1;\n" ::: "memory")
#define CP_WAITALL() asm volatile("cp.async.wait_all;\n" ::: "memory")

// fp16 m16n8k16, fp32 accumulate
__device__ __forceinline__ void mma_f16(float* c, const uint32_t* a,
                                        const uint32_t* b)
{
    asm volatile("mma.sync.aligned.m16n8k16.row.col.f32.f16.f16.f32 "
                 "{%0,%1,%2,%3}, {%4,%5,%6,%7}, {%8,%9}, {%0,%1,%2,%3};\n"
                 : "+f"(c[0]), "+f"(c[1]), "+f"(c[2]), "+f"(c[3])
                 : "r"(a[0]), "r"(a[1]), "r"(a[2]), "r"(a[3]),
                   "r"(b[0]), "r"(b[1]));
}

__device__ __forceinline__ uint32_t pack2(float lo, float hi)
{
    __half2 h = __floats2half2_rn(lo, hi);
    return *(uint32_t*)&h;
}

// ---------------- merged weight convert + k-pair interleave -----------------------
// segments: [0,1536) Wqkv N=3072 | [1536,2048) Wout N=1024 |
//           [2048,4096) W1 N=4096 | [4096,6144) W2 N=1024 (K=4096)
__global__ void wconv_all(const float* __restrict__ Wqkv,
                          const float* __restrict__ Wout,
                          const float* __restrict__ W1,
                          const float* __restrict__ W2,
                          __half* __restrict__ o_qkv,
                          __half* __restrict__ o_out,
                          __half* __restrict__ o_w1,
                          __half* __restrict__ o_w2)
{
    int bid = blockIdx.x;
    const float* in;  __half* out;  int N;  int base;
    if (bid < 1536)      { in = Wqkv; out = o_qkv; N = 3*D_; base = 0; }
    else if (bid < 2048) { in = Wout; out = o_out; N = D_;   base = 1536; }
    else if (bid < 4096) { in = W1;   out = o_w1;  N = DFF_; base = 2048; }
    else                 { in = W2;   out = o_w2;  N = D_;   base = 4096; }
    int idx = (bid - base)*256 + threadIdx.x;
    int k2 = idx / (N >> 2);
    int nc = (idx - k2*(N >> 2)) * 4;
    float4 e = *(const float4*)(in + (size_t)(2*k2    )*N + nc);
    float4 o = *(const float4*)(in + (size_t)(2*k2 + 1)*N + nc);
    uint4 r;
    r.x = pack2(e.x, o.x);  r.y = pack2(e.y, o.y);
    r.z = pack2(e.z, o.z);  r.w = pack2(e.w, o.w);
    *(uint4*)(out + ((size_t)k2*N + nc)*2) = r;
}

// ---------------- adaLN modulation ------------------------------------------------
__global__ void mod_kernel(const float* __restrict__ c,
                           const float* __restrict__ adaW,
                           const float* __restrict__ adab,
                           float* __restrict__ mod)
{
    int b = blockIdx.y;
    int j = blockIdx.x * 256 + threadIdx.x;
    __shared__ float cs[D_];
    for (int i = threadIdx.x; i < D_; i += 256) cs[i] = c[b*D_ + i];
    __syncthreads();
    float acc = adab[j];
#pragma unroll 4
    for (int k = 0; k < D_; k++)
        acc = fmaf(cs[k], adaW[(size_t)k*SIXD_ + j], acc);
    mod[b*SIXD_ + j] = acc;
}

// ---------------- LayerNorm + modulate (half output) ------------------------------
__global__ void ln_mod_kernel(const float* __restrict__ x,
                              const float* __restrict__ w,
                              const float* __restrict__ mod,
                              __half* __restrict__ out,
                              int sh_off, int sc_off)
{
    int t = blockIdx.x;
    int b = t / S_;
    int tid = threadIdx.x;
    float4 v = ((const float4*)(x + (size_t)t*D_))[tid];
    float s  = v.x + v.y + v.z + v.w;
    float sq = v.x*v.x + v.y*v.y + v.z*v.z + v.w*v.w;
#pragma unroll
    for (int o = 16; o > 0; o >>= 1) {
        s  += __shfl_xor_sync(0xffffffffu, s,  o);
        sq += __shfl_xor_sync(0xffffffffu, sq, o);
    }
    __shared__ float ss[8], ssq[8];
    int warp = tid >> 5, lane = tid & 31;
    if (lane == 0) { ss[warp] = s; ssq[warp] = sq; }
    __syncthreads();
    if (warp == 0) {
        s  = (lane < 8) ? ss[lane]  : 0.f;
        sq = (lane < 8) ? ssq[lane] : 0.f;
#pragma unroll
        for (int o = 4; o > 0; o >>= 1) {
            s  += __shfl_xor_sync(0xffffffffu, s,  o);
            sq += __shfl_xor_sync(0xffffffffu, sq, o);
        }
        if (lane == 0) { ss[0] = s; ssq[0] = sq; }
    }
    __syncthreads();
    s = ss[0]; sq = ssq[0];
    float mu   = s  * (1.f/D_);
    float var  = sq * (1.f/D_) - mu*mu;
    float rsig = rsqrtf(var + 1e-5f);

    const float* modb = mod + b*SIXD_;
    float4 wv  = ((const float4*)w)[tid];
    float4 shv = ((const float4*)(modb + sh_off))[tid];
    float4 scv = ((const float4*)(modb + sc_off))[tid];
    uint2 r;
    r.x = pack2(fmaf((v.x-mu)*rsig*wv.x, (1.f+scv.x), shv.x),
                fmaf((v.y-mu)*rsig*wv.y, (1.f+scv.y), shv.y));
    r.y = pack2(fmaf((v.z-mu)*rsig*wv.z, (1.f+scv.z), shv.z),
                fmaf((v.w-mu)*rsig*wv.w, (1.f+scv.w), shv.w));
    *(uint2*)(out + (size_t)t*D_ + tid*4) = r;
}

// ---------------- RMSNorm(q,k) + RoPE + relayout (vectorized half2 loads) ---------
// Lane owns elements (2*lane, 2*lane+1); RoPE partner j±32 lives in lane^16
// (recovered via shfl_xor), sign = -1 for lane<16 else +1.
// q scale folds softmax 1/sqrt(HD) AND log2(e)
#define QSCALE 0.1803368801111204f
__global__ void qk_rope_kernel(const __half* __restrict__ qkv,
                               const float* __restrict__ cosp,
                               const float* __restrict__ sinp,
                               const float* __restrict__ qw,
                               const float* __restrict__ kw,
                               __half* __restrict__ Q,
                               __half* __restrict__ K,
                               __half* __restrict__ V)
{
    int t = blockIdx.x;
    int s = t % S_;
    int b = t / S_;
    int h    = threadIdx.x >> 5;
    int lane = threadIdx.x & 31;
    int l2   = lane * 2;
    const __half* base = qkv + (size_t)t*3*D_ + h*HD_;
    float2 qv = __half22float2(*(const __half2*)(base + l2));
    float2 kv = __half22float2(*(const __half2*)(base + D_ + l2));
    float2 vv = __half22float2(*(const __half2*)(base + 2*D_ + l2));
    float q0 = qv.x, q1 = qv.y;
    float k0 = kv.x, k1 = kv.y;

    float qs = q0*q0 + q1*q1;
    float ks = k0*k0 + k1*k1;
#pragma unroll
    for (int o = 16; o > 0; o >>= 1) {
        qs += __shfl_xor_sync(0xffffffffu, qs, o);
        ks += __shfl_xor_sync(0xffffffffu, ks, o);
    }
    float qr = rsqrtf(qs*(1.f/HD_) + 1e-6f);
    float kr = rsqrtf(ks*(1.f/HD_) + 1e-6f);
    float2 qwv = *(const float2*)(qw + l2);
    float2 kwv = *(const float2*)(kw + l2);
    q0 *= qr*qwv.x;  q1 *= qr*qwv.y;
    k0 *= kr*kwv.x;  k1 *= kr*kwv.y;

    // exchange rotate-half partners (lane^16 holds elements j±32)
    float oq0 = __shfl_xor_sync(0xffffffffu, q0, 16);
    float oq1 = __shfl_xor_sync(0xffffffffu, q1, 16);
    float ok0 = __shfl_xor_sync(0xffffffffu, k0, 16);
    float ok1 = __shfl_xor_sync(0xffffffffu, k1, 16);
    float sgn = (lane < 16) ? -1.f : 1.f;

    float2 cs = *(const float2*)(cosp + s*HD_ + l2);
    float2 sn = *(const float2*)(sinp + s*HD_ + l2);
    float qo0 = (q0*cs.x + sgn*oq0*sn.x) * QSCALE;
    float qo1 = (q1*cs.y + sgn*oq1*sn.y) * QSCALE;
    float ko0 =  k0*cs.x + sgn*ok0*sn.x;
    float ko1 =  k1*cs.y + sgn*ok1*sn.y;

    int bh = b*H_ + h;
    size_t o = ((size_t)bh*S_ + s)*HD_;
    *(__half2*)(Q + o + l2) = __floats2half2_rn(qo0, qo1);
    *(__half2*)(K + o + l2) = __floats2half2_rn(ko0, ko1);
    // V pair-interleaved along s: V[((bh*S/2 + s/2)*HD + hd)*2 + (s&1)]
    size_t vb = ((size_t)bh*(S_/2) + (s >> 1))*HD_;
    V[(vb + l2    )*2 + (s & 1)] = __float2half_rn(vv.x);
    V[(vb + l2 + 1)*2 + (s & 1)] = __float2half_rn(vv.y);
}

// ================= fp16 tensor-core flash attention (R12 proven) ==================
// No online max (|s|<=8 bound); Q/P in registers; K/V double-buffered.
#define AQT 128
#define AKT 64
#define QP2 36
#define KP2 36
#define VP2 72
#define QS_W (AQT*QP2)          // 4608 words
#define KS_W (AKT*KP2)          // 2304
#define VS_W ((AKT/2)*VP2)      // 2304
#define ATTN_SMEM ((QS_W + 2*(KS_W + VS_W)) * 4)   // 55296 B

__global__ __launch_bounds__(256, 2)
void attn_mma_kernel(const __half* __restrict__ Q,
                     const __half* __restrict__ K,
                     const __half* __restrict__ V,
                     __half* __restrict__ out)
{
    extern __shared__ uint32_t smu[];
    uint32_t* Qs = smu;
    uint32_t* Kst[2]; uint32_t* Vst[2];
    Kst[0] = Qs + QS_W;           Vst[0] = Kst[0] + KS_W;
    Kst[1] = Vst[0] + VS_W;       Vst[1] = Kst[1] + KS_W;

    int bh  = blockIdx.y;
    int qt  = blockIdx.x;
    int tid = threadIdx.x;
    int warp = tid >> 5, lane = tid & 31;
    int gid = lane >> 2, tig = lane & 3;
    int wm = warp * 16;

    const __half* Kb0 = K + (size_t)bh*S_*HD_;
    const __half* Vb0 = V + (size_t)bh*(S_/2)*HD_*2;

    // ---- group 0: Q tile + KV tile 0 ---------------------------------------------
    const __half* Qb = Q + ((size_t)bh*S_ + qt*AQT)*HD_;
    {
        int qr = tid >> 1, qc2 = (tid & 1) * 16;
#pragma unroll
        for (int c = 0; c < 4; c++)
            cp_async16(&Qs[qr*QP2 + qc2 + c*4], Qb + qr*HD_ + (qc2 + c*4)*2);
    }
    {
        int kr = tid >> 2, kc2 = (tid & 3) * 8;
        const __half* Kb = Kb0 + (size_t)kr*HD_;
        cp_async16(&Kst[0][kr*KP2 + kc2    ], Kb + kc2*2);
        cp_async16(&Kst[0][kr*KP2 + kc2 + 4], Kb + kc2*2 + 8);
        int vr = tid >> 3, vc2 = (tid & 7) * 8;
        const __half* Vb = Vb0 + ((size_t)vr*HD_ + vc2)*2;
        cp_async16(&Vst[0][vr*VP2 + vc2    ], Vb);
        cp_async16(&Vst[0][vr*VP2 + vc2 + 4], Vb + 8);
    }
    CP_COMMIT();

    float l0 = 0.f, l1 = 0.f;        // per-thread partial row sums
    float oacc[8][4];
#pragma unroll
    for (int j = 0; j < 8; j++)
#pragma unroll
        for (int q = 0; q < 4; q++) oacc[j][q] = 0.f;

    uint32_t qf[4][4];               // Q fragments, loaded once at kt==0

    const int NT = S_/AKT;
    for (int kt = 0; kt < NT; kt++) {
        int s = kt & 1;
        if (kt + 1 < NT) {
            // prefetch KV(kt+1) into the other stage
            int kr = tid >> 2, kc2 = (tid & 3) * 8;
            const __half* Kb = Kb0 + (size_t)((kt+1)*AKT + kr)*HD_;
            cp_async16(&Kst[s^1][kr*KP2 + kc2    ], Kb + kc2*2);
            cp_async16(&Kst[s^1][kr*KP2 + kc2 + 4], Kb + kc2*2 + 8);
            int vr = tid >> 3, vc2 = (tid & 7) * 8;
            const __half* Vb = Vb0 + ((size_t)((kt+1)*(AKT/2) + vr)*HD_ + vc2)*2;
            cp_async16(&Vst[s^1][vr*VP2 + vc2    ], Vb);
            cp_async16(&Vst[s^1][vr*VP2 + vc2 + 4], Vb + 8);
            CP_COMMIT();
            CP_WAIT1();         // current stage resident, prefetch in flight
        } else {
            CP_WAITALL();
        }
        __syncthreads();

        if (kt == 0) {
            // hoist Q fragments into registers (Qs never read again)
#pragma unroll
            for (int kc = 0; kc < 4; kc++) {
                const uint32_t* qp = Qs + (wm + gid)*QP2 + kc*8 + tig;
                qf[kc][0] = qp[0];
                qf[kc][1] = qp[8*QP2];
                qf[kc][2] = qp[4];
                qf[kc][3] = qp[8*QP2 + 4];
            }
        }

        const uint32_t* Ks = Kst[s];
        const uint32_t* Vs = Vst[s];

        // ---- S = Q @ K^T (scores pre-scaled by log2e/sqrt(HD)) -----------------
        float sacc[8][4];
#pragma unroll
        for (int j = 0; j < 8; j++)
#pragma unroll
            for (int q = 0; q < 4; q++) sacc[j][q] = 0.f;

#pragma unroll
        for (int kc = 0; kc < 4; kc++) {
#pragma unroll
            for (int j = 0; j < 8; j++) {
                uint32_t bf[2];
                const uint32_t* kp = Ks + (j*8 + gid)*KP2 + kc*8 + tig;
                bf[0] = kp[0];
                bf[1] = kp[4];
                mma_f16(sacc[j], qf[kc], bf);
            }
        }

        // ---- p = 2^s (no max-shift; fp16-safe) ---------------------------------
        uint32_t p2a[8], p2b[8];
#pragma unroll
        for (int j = 0; j < 8; j++) {
            __half2 pa = __floats2half2_rn(exp2f(sacc[j][0]), exp2f(sacc[j][1]));
            __half2 pb = __floats2half2_rn(exp2f(sacc[j][2]), exp2f(sacc[j][3]));
            float2 fa = __half22float2(pa);
            float2 fb = __half22float2(pb);
            l0 += fa.x + fa.y;  l1 += fb.x + fb.y;
            p2a[j] = *(uint32_t*)&pa;
            p2b[j] = *(uint32_t*)&pb;
        }

        // ---- O += P @ V (A-fragments direct from registers) --------------------
#pragma unroll
        for (int kc = 0; kc < 4; kc++) {
            uint32_t af[4];
            af[0] = p2a[2*kc];
            af[1] = p2b[2*kc];
            af[2] = p2a[2*kc + 1];
            af[3] = p2b[2*kc + 1];
#pragma unroll
            for (int j = 0; j < 8; j++) {
                uint32_t bf[2];
                const uint32_t* vp = Vs + (kc*8 + tig)*VP2 + j*8 + gid;
                bf[0] = vp[0];
                bf[1] = vp[4*VP2];
                mma_f16(oacc[j], af, bf);
            }
        }
        __syncthreads();   // all warps done with stage s before it is refilled
    }

    // ---- final l reduction + epilogue -> g_attn (half) ---------------------------
    l0 += __shfl_xor_sync(0xffffffffu, l0, 1);
    l0 += __shfl_xor_sync(0xffffffffu, l0, 2);
    l1 += __shfl_xor_sync(0xffffffffu, l1, 1);
    l1 += __shfl_xor_sync(0xffffffffu, l1, 2);

    int b = bh >> 4, h = bh & 15;
    int r0 = qt*AQT + wm + gid;
    float inv0 = 1.f / l0, inv1 = 1.f / l1;
#pragma unroll
    for (int j = 0; j < 8; j++) {
        int col = h*HD_ + j*8 + 2*tig;
        *(__half2*)&out[((size_t)(b*S_ + r0    ))*D_ + col] =
            __floats2half2_rn(oacc[j][0]*inv0, oacc[j][1]*inv0);
        *(__half2*)&out[((size_t)(b*S_ + r0 + 8))*D_ + col] =
            __floats2half2_rn(oacc[j][2]*inv1, oacc[j][3]*inv1);
    }
}

// ================= fp16 tensor-core GEMM (R12 proven: GBK=32, wait_group 1) =======
#define GBM 128
#define GBN 128
#define GBK 32
#define AP2 20
#define BP2 136

__device__ __forceinline__ float gelu_t(float x)
{
    float x3 = x*x*x;
    return 0.5f*x*(1.f + tanhf(0.7978845608028654f*(x + 0.044715f*x3)));
}

// MODE 0: C(half) = acc                       (QKV)
// MODE 1: C(float) = res + gate*acc           (out-proj + residual)
// MODE 2: C(half) = gelu(acc + bias)          (MLP up)
// MODE 3: C(float) = res + gate*(acc + bias)  (MLP down + residual)
template <int MODE>
__global__ __launch_bounds__(256)
void mma_gemm(const __half* __restrict__ A, const __half* __restrict__ Bm,
              void* __restrict__ Cv, int N, int K,
              const float* __restrict__ res, const float* __restrict__ bias,
              const float* __restrict__ mod, int gate_off)
{
    __shared__ uint32_t As[2][GBM*AP2];
    __shared__ uint32_t Bs[2][16*BP2];

    int tid  = threadIdx.x;
    int warp = tid >> 5, lane = tid & 31;
    int wm   = (warp >> 2) * 64;
    int wn   = (warp & 3)  * 32;
    int gid  = lane >> 2;
    int tig  = lane & 3;

    const __half* Ap = A  + (size_t)blockIdx.y * GBM * K;
    const __half* Bp = Bm + (size_t)blockIdx.x * GBN * 2;

    int ar  = tid >> 1;
    int ac2 = (tid & 1) * 8;
    int bk2 = tid >> 4;
    int bn2 = (tid & 15) * 8;

    float acc[4][4][4];
#pragma unroll
    for (int i = 0; i < 4; i++)
#pragma unroll
        for (int j = 0; j < 4; j++)
#pragma unroll
            for (int q = 0; q < 4; q++) acc[i][j][q] = 0.f;

    {
        const __half* ag = Ap + (size_t)ar*K + ac2*2;
        cp_async16(&As[0][ar*AP2 + ac2],     ag);
        cp_async16(&As[0][ar*AP2 + ac2 + 4], ag + 8);
        const __half* bg = Bp + ((size_t)bk2*N + bn2)*2;
        cp_async16(&Bs[0][bk2*BP2 + bn2],     bg);
        cp_async16(&Bs[0][bk2*BP2 + bn2 + 4], bg + 8);
    }
    CP_COMMIT();

    int buf = 0;
    for (int k0 = 0; k0 < K; k0 += GBK) {
        if (k0 + GBK < K) {
            const __half* ag = Ap + (size_t)ar*K + (k0 + GBK) + ac2*2;
            cp_async16(&As[buf^1][ar*AP2 + ac2],     ag);
            cp_async16(&As[buf^1][ar*AP2 + ac2 + 4], ag + 8);
            const __half* bg = Bp + ((size_t)((k0 + GBK)/2 + bk2)*N + bn2)*2;
            cp_async16(&Bs[buf^1][bk2*BP2 + bn2],     bg);
            cp_async16(&Bs[buf^1][bk2*BP2 + bn2 + 4], bg + 8);
        }
        CP_COMMIT();
        CP_WAIT1();
        __syncthreads();

        const uint32_t* as = As[buf];
        const uint32_t* bs = Bs[buf];
#pragma unroll
        for (int kc = 0; kc < 2; kc++) {
            uint32_t af[4][4], bf[4][2];
#pragma unroll
            for (int i = 0; i < 4; i++) {
                int r0 = wm + i*16 + gid;
                const uint32_t* ap = as + r0*AP2 + kc*8 + tig;
                af[i][0] = ap[0];
                af[i][1] = ap[8*AP2];
                af[i][2] = ap[4];
                af[i][3] = ap[8*AP2 + 4];
            }
#pragma unroll
            for (int j = 0; j < 4; j++) {
                int n0 = wn + j*8 + gid;
                bf[j][0] = bs[(kc*8 + tig    )*BP2 + n0];
                bf[j][1] = bs[(kc*8 + tig + 4)*BP2 + n0];
            }
#pragma unroll
            for (int i = 0; i < 4; i++)
#pragma unroll
                for (int j = 0; j < 4; j++)
                    mma_f16(acc[i][j], af[i], bf[j]);
        }
        __syncthreads();
        buf ^= 1;
    }

    int row_base = blockIdx.y*GBM + wm;
    int col_base = blockIdx.x*GBN + wn;
    int bb = (blockIdx.y * GBM) >> 11;
    const float* modb = (MODE == 1 || MODE == 3)
                      ? (mod + bb*SIXD_ + gate_off) : nullptr;
#pragma unroll
    for (int i = 0; i < 4; i++) {
        int r0 = row_base + i*16 + gid;
#pragma unroll
        for (int j = 0; j < 4; j++) {
            int c0 = col_base + j*8 + tig*2;
#pragma unroll
            for (int h = 0; h < 2; h++) {
                int row = r0 + h*8;
                float v0 = acc[i][j][h*2 + 0];
                float v1 = acc[i][j][h*2 + 1];
                if (MODE == 0) {
                    *(__half2*)((__half*)Cv + (size_t)row*N + c0) =
                        __floats2half2_rn(v0, v1);
                } else if (MODE == 1) {
                    float2 rv = *(const float2*)(res + (size_t)row*N + c0);
                    float2 st;
                    st.x = rv.x + modb[c0    ]*v0;
                    st.y = rv.y + modb[c0 + 1]*v1;
                    *(float2*)((float*)Cv + (size_t)row*N + c0) = st;
                } else if (MODE == 2) {
                    *(__half2*)((__half*)Cv + (size_t)row*N + c0) =
                        __floats2half2_rn(gelu_t(v0 + bias[c0]),
                                          gelu_t(v1 + bias[c0 + 1]));
                } else {
                    float2 rv = *(const float2*)(res + (size_t)row*N + c0);
                    float2 st;
                    st.x = rv.x + modb[c0    ]*(v0 + bias[c0]);
                    st.y = rv.y + modb[c0 + 1]*(v1 + bias[c0 + 1]);
                    *(float2*)((float*)Cv + (size_t)row*N + c0) = st;
                }
            }
        }
    }
}

// ---------------- launch ---------------------------------------------------------
extern "C" void kernel_launch(void* const* d_in, const int* in_sizes, int n_in,
                              void* d_out, int out_size)
{
    const float* x      = (const float*)d_in[0];
    const float* cosp   = (const float*)d_in[1];
    const float* sinp   = (const float*)d_in[2];
    const float* c      = (const float*)d_in[3];
    const float* n1w    = (const float*)d_in[4];
    const float* Wqkv   = (const float*)d_in[5];
    const float* Wout   = (const float*)d_in[6];
    const float* qw     = (const float*)d_in[7];
    const float* kw     = (const float*)d_in[8];
    const float* n2w    = (const float*)d_in[9];
    const float* W1     = (const float*)d_in[10];
    const float* b1     = (const float*)d_in[11];
    const float* W2     = (const float*)d_in[12];
    const float* b2     = (const float*)d_in[13];
    const float* adaW   = (const float*)d_in[14];
    const float* adab   = (const float*)d_in[15];
    float* out = (float*)d_out;

    float *p_mod, *p_x2;
    __half *p_xn, *p_qkv, *p_q, *p_k, *p_v, *p_attn, *p_h;
    __half *p_wqkv, *p_wout, *p_w1, *p_w2;
    cudaGetSymbolAddress((void**)&p_mod,  g_mod);
    cudaGetSymbolAddress((void**)&p_xn,   g_xn);
    cudaGetSymbolAddress((void**)&p_qkv,  g_qkv);
    cudaGetSymbolAddress((void**)&p_q,    g_q);
    cudaGetSymbolAddress((void**)&p_k,    g_k);
    cudaGetSymbolAddress((void**)&p_v,    g_v);
    cudaGetSymbolAddress((void**)&p_attn, g_attn);
    cudaGetSymbolAddress((void**)&p_x2,   g_x2);
    cudaGetSymbolAddress((void**)&p_h,    g_h);
    cudaGetSymbolAddress((void**)&p_wqkv, g_wqkv);
    cudaGetSymbolAddress((void**)&p_wout, g_wout);
    cudaGetSymbolAddress((void**)&p_w1,   g_w1);
    cudaGetSymbolAddress((void**)&p_w2,   g_w2);

    cudaFuncSetAttribute(attn_mma_kernel,
                         cudaFuncAttributeMaxDynamicSharedMemorySize, ATTN_SMEM);

    // 0. merged weight convert + k-pair interleave to half
    wconv_all<<<6144, 256>>>(Wqkv, Wout, W1, W2,
                             p_wqkv, p_wout, p_w1, p_w2);

    // 1. adaLN modulation
    mod_kernel<<<dim3(SIXD_/256, B_), 256>>>(c, adaW, adab, p_mod);
    // 2. LN1 + modulate -> half
    ln_mod_kernel<<<T_, 256>>>(x, n1w, p_mod, p_xn, 0, D_);
    // 3. QKV projection (fp16 mma) -> half
    mma_gemm<0><<<dim3(3*D_/GBN, T_/GBM), 256>>>(p_xn, p_wqkv, p_qkv,
                                                 3*D_, D_, nullptr, nullptr,
                                                 nullptr, 0);
    // 4. qk-RMSNorm + RoPE + relayout -> half (vectorized; q pre-scaled log2e/8)
    qk_rope_kernel<<<T_, 512>>>(p_qkv, cosp, sinp, qw, kw, p_q, p_k, p_v);
    // 5. attention (fp16 mma flash, no-max softmax, register Q/P)
    attn_mma_kernel<<<dim3(S_/AQT, B_*H_), 256, ATTN_SMEM>>>(p_q, p_k, p_v,
                                                             p_attn);
    // 6. out-proj + gated residual (gate g_msa @2D) -> float
    mma_gemm<1><<<dim3(D_/GBN, T_/GBM), 256>>>(p_attn, p_wout, p_x2,
                                               D_, D_, x, nullptr,
                                               p_mod, 2*D_);
    // 7. LN2 + modulate (shift 3D, scale 4D) -> half
    ln_mod_kernel<<<T_, 256>>>(p_x2, n2w, p_mod, p_xn, 3*D_, 4*D_);
    // 8. MLP up + gelu -> half
    mma_gemm<2><<<dim3(DFF_/GBN, T_/GBM), 256>>>(p_xn, p_w1, p_h,
                                                 DFF_, D_, nullptr, b1,
                                                 nullptr, 0);
    // 9. MLP down + gated residual (gate g_mlp @5D) -> float (d_out)
    mma_gemm<3><<<dim3(D_/GBN, T_/GBM), 256>>>(p_h, p_w2, out,
                                               D_, DFF_, p_x2, b2,
                                               p_mod, 5*D_);
}